// round 3
// baseline (speedup 1.0000x reference)
#include <cuda_runtime.h>
#include <cuda_bf16.h>

#define T_STEPS 512
#define BATCH   32
#define DIM     1024
#define NS      64
#define M_TOT   (T_STEPS * BATCH)   // 16384

typedef unsigned long long ull;

// Scratch: projections [t][b][{k,q,v,ax}][64]  (16 MB, L2-resident during scan)
__device__ __align__(16) float  g_proj[(size_t)M_TOT * 256];
// kk[t][b] = { k_t·k_{t+1}, k_t·k_{t+2}, k_t·k_{t+3}, 0 }  (zero-padded at end)
__device__ __align__(16) float4 g_kk[M_TOT];

// ---------------------------------------------------------------------------
// Packed f32x2 helpers (Blackwell FFMA2: 2 fp32 FMA per instruction)
// ---------------------------------------------------------------------------
__device__ __forceinline__ void ffma2(ull& d, ull a, ull b) {
    asm("fma.rn.f32x2 %0, %1, %2, %0;" : "+l"(d) : "l"(a), "l"(b));
}
__device__ __forceinline__ float2 upk(ull u) {
    float2 r; asm("mov.b64 {%0, %1}, %2;" : "=f"(r.x), "=f"(r.y) : "l"(u)); return r;
}

// ---------------------------------------------------------------------------
// Projection GEMM: C[m][n] = sum_d X[m][d] * W[n][d]
// grid (M/128, 4): y selects W (0=k,1=q,2=v,3=ax) -> column block y*64 of g_proj.
// BM=128, BN=64, BK=32, 128 threads, 8x8 per thread via FFMA2 (row-paired).
// ---------------------------------------------------------------------------
__global__ __launch_bounds__(128) void proj_gemm(
    const float* __restrict__ X,
    const float* __restrict__ Wk, const float* __restrict__ Wq,
    const float* __restrict__ Wv, const float* __restrict__ Wa)
{
    __shared__ float  Xs[32][128];   // [k][m]
    __shared__ float2 Ws2[32][64];   // [k][n], value duplicated in both halves

    const float* W = (blockIdx.y == 0) ? Wk :
                     (blockIdx.y == 1) ? Wq :
                     (blockIdx.y == 2) ? Wv : Wa;

    const int tid = threadIdx.x;
    const int m0  = blockIdx.x * 128;
    const int ty  = tid >> 3;   // 0..15 -> 8 rows
    const int tx  = tid & 7;    // 0..7  -> 8 cols

    ull acc[4][8];               // [row-pair][col]; lo lane = even row
    #pragma unroll
    for (int i = 0; i < 4; i++)
        #pragma unroll
        for (int j = 0; j < 8; j++) acc[i][j] = 0ull;

    for (int k0 = 0; k0 < DIM; k0 += 32) {
        __syncthreads();
        // X tile 128x32: thread loads its row (m = m0+tid), 8 float4 across k
        #pragma unroll
        for (int i = 0; i < 8; i++) {
            float4 v = *(const float4*)(X + (size_t)(m0 + tid) * DIM + k0 + i * 4);
            Xs[i * 4 + 0][tid] = v.x;
            Xs[i * 4 + 1][tid] = v.y;
            Xs[i * 4 + 2][tid] = v.z;
            Xs[i * 4 + 3][tid] = v.w;
        }
        // W tile 64x32, duplicated into float2
        #pragma unroll
        for (int i = 0; i < 4; i++) {
            int n  = tid & 63;
            int kq = i * 2 + (tid >> 6);
            float4 v = *(const float4*)(W + (size_t)n * DIM + k0 + kq * 4);
            Ws2[kq * 4 + 0][n] = make_float2(v.x, v.x);
            Ws2[kq * 4 + 1][n] = make_float2(v.y, v.y);
            Ws2[kq * 4 + 2][n] = make_float2(v.z, v.z);
            Ws2[kq * 4 + 3][n] = make_float2(v.w, v.w);
        }
        __syncthreads();

        #pragma unroll
        for (int kk = 0; kk < 32; kk++) {
            const ull* ar = (const ull*)&Xs[kk][ty * 8];
            ull ap0 = ar[0], ap1 = ar[1], ap2 = ar[2], ap3 = ar[3];
            const ull* wr = (const ull*)&Ws2[kk][tx * 8];
            ull wp[8];
            #pragma unroll
            for (int p = 0; p < 8; p++) wp[p] = wr[p];
            #pragma unroll
            for (int j = 0; j < 8; j++) {
                ffma2(acc[0][j], ap0, wp[j]);
                ffma2(acc[1][j], ap1, wp[j]);
                ffma2(acc[2][j], ap2, wp[j]);
                ffma2(acc[3][j], ap3, wp[j]);
            }
        }
    }

    // Store: row m = m0+ty*8+i, col = blockIdx.y*64 + tx*8 + j
    #pragma unroll
    for (int i = 0; i < 8; i++) {
        float c[8];
        #pragma unroll
        for (int j = 0; j < 8; j++) {
            float2 v = upk(acc[i >> 1][j]);
            c[j] = (i & 1) ? v.y : v.x;
        }
        float* dst = g_proj + (size_t)(m0 + ty * 8 + i) * 256 + blockIdx.y * 64 + tx * 8;
        *(float4*)(dst + 0) = make_float4(c[0], c[1], c[2], c[3]);
        *(float4*)(dst + 4) = make_float4(c[4], c[5], c[6], c[7]);
    }
}

// ---------------------------------------------------------------------------
// kk kernel: g_kk[t][b] = {k_t·k_{t+1}, k_t·k_{t+2}, k_t·k_{t+3}, 0}, zero-padded.
// One thread per (t,b). 16384 threads, all L2 hits.
// ---------------------------------------------------------------------------
__global__ __launch_bounds__(128) void kk_kernel()
{
    int idx = blockIdx.x * 128 + threadIdx.x;       // 0..16383
    int t = idx >> 5;
    int b = idx & 31;

    const float4* p0 = (const float4*)(g_proj + (size_t)(t * 32 + b) * 256);
    int t1 = (t + 1 < T_STEPS) ? t + 1 : t;
    int t2 = (t + 2 < T_STEPS) ? t + 2 : t;
    int t3 = (t + 3 < T_STEPS) ? t + 3 : t;
    const float4* p1 = (const float4*)(g_proj + (size_t)(t1 * 32 + b) * 256);
    const float4* p2 = (const float4*)(g_proj + (size_t)(t2 * 32 + b) * 256);
    const float4* p3 = (const float4*)(g_proj + (size_t)(t3 * 32 + b) * 256);

    float a1 = 0.f, a2 = 0.f, a3 = 0.f;
    #pragma unroll
    for (int i = 0; i < 16; i++) {
        float4 k0 = p0[i];
        float4 q1 = p1[i], q2 = p2[i], q3 = p3[i];
        a1 += k0.x * q1.x + k0.y * q1.y + k0.z * q1.z + k0.w * q1.w;
        a2 += k0.x * q2.x + k0.y * q2.y + k0.z * q2.z + k0.w * q2.w;
        a3 += k0.x * q3.x + k0.y * q3.y + k0.z * q3.z + k0.w * q3.w;
    }
    if (t + 1 >= T_STEPS) a1 = 0.f;
    if (t + 2 >= T_STEPS) a2 = 0.f;
    if (t + 3 >= T_STEPS) a3 = 0.f;
    g_kk[idx] = make_float4(a1, a2, a3, 0.f);
}

// ---------------------------------------------------------------------------
// Scan with 3-level lookahead recurrence.
// Per row i (all per-row scalars):
//   alpha_t = sigmoid(ax_t + da*r_t + ba)
//   r_{t+1} = alpha*A1 + (1-alpha)*v_t*kk1_t      (A1 = S_{t-1}·k_{t+1})
//   A1'     = alpha*A2 + (1-alpha)*v_t*kk2_t      (A2 = S_{t-1}·k_{t+2})
//   A2'     = alpha*A3 + (1-alpha)*v_t*kk3_t      (A3 = S_{t-1}·k_{t+3})
//   S_t     = alpha*S_{t-1} + (1-alpha)*v_t*k_t
//   A3'     = S_t·k_{t+4}   (dot + 3 shuffles, 3 steps of slack)
//   h_t     = S_t·q_t  ->  out = h^2 * sigmoid(h)   (off critical path)
// Grid: 128 CTAs (4 per batch, 16 rows each), 128 threads; thread=(row, 8-col slice).
// ---------------------------------------------------------------------------
__global__ __launch_bounds__(128) void scan_kernel(
    const float* __restrict__ S_in,
    const float* __restrict__ d_alpha,
    const float* __restrict__ b_alpha,
    float* __restrict__ out)
{
    const int b   = blockIdx.x >> 2;
    const int rg  = blockIdx.x & 3;
    const int tid = threadIdx.x;
    const int rl  = tid >> 3;        // 0..15
    const int g   = tid & 7;         // 0..7
    const int row = rg * 16 + rl;
    const int c0  = g * 8;

    float S[8];
    {
        const float* sp = S_in + ((size_t)b * NS + row) * NS + c0;
        #pragma unroll
        for (int j = 0; j < 8; j++) S[j] = sp[j];
    }
    const float da = d_alpha[row];
    const float ba = b_alpha[row];

    // Rings: K depth 8 (k_t used at t for update and at t-4 for the A3 dot),
    // Q / scalars depth 4 (prefetch distance 4 steps).
    float  K[8][8];
    float  Q[4][8];
    float4 KK[4];
    float  Vv[4], AxB[4];

    auto loadK = [&](int slot, int t) {
        const float4* p = (const float4*)(g_proj + (size_t)(t * 32 + b) * 256 + c0);
        float4 x0 = p[0], x1 = p[1];
        K[slot][0]=x0.x; K[slot][1]=x0.y; K[slot][2]=x0.z; K[slot][3]=x0.w;
        K[slot][4]=x1.x; K[slot][5]=x1.y; K[slot][6]=x1.z; K[slot][7]=x1.w;
    };
    auto loadQ = [&](int slot, int t) {
        const float4* p = (const float4*)(g_proj + (size_t)(t * 32 + b) * 256 + 64 + c0);
        float4 x0 = p[0], x1 = p[1];
        Q[slot][0]=x0.x; Q[slot][1]=x0.y; Q[slot][2]=x0.z; Q[slot][3]=x0.w;
        Q[slot][4]=x1.x; Q[slot][5]=x1.y; Q[slot][6]=x1.z; Q[slot][7]=x1.w;
    };
    auto loadScal = [&](int slot, int t) {
        size_t base = (size_t)(t * 32 + b) * 256;
        Vv[slot]  = g_proj[base + 128 + row];
        AxB[slot] = g_proj[base + 192 + row] + ba;
        KK[slot]  = g_kk[t * 32 + b];
    };

    auto red8 = [](float x) {
        x += __shfl_xor_sync(0xffffffffu, x, 1);
        x += __shfl_xor_sync(0xffffffffu, x, 2);
        x += __shfl_xor_sync(0xffffffffu, x, 4);
        return x;
    };

    // Prologue: fill rings, compute r0/A1/A2/A3 against S_init.
    #pragma unroll
    for (int j = 0; j < 8; j++) loadK(j, j);
    #pragma unroll
    for (int j = 0; j < 4; j++) { loadQ(j, j); loadScal(j, j); }

    float r, A1, A2, A3;
    {
        float t0=0.f, t1=0.f, t2=0.f, t3=0.f;
        #pragma unroll
        for (int j = 0; j < 8; j++) {
            t0 = fmaf(S[j], K[0][j], t0);
            t1 = fmaf(S[j], K[1][j], t1);
            t2 = fmaf(S[j], K[2][j], t2);
            t3 = fmaf(S[j], K[3][j], t3);
        }
        r = red8(t0); A1 = red8(t1); A2 = red8(t2); A3 = red8(t3);
    }

    float* outp = out + (size_t)b * NS + row;   // advance by 32*64 per step

    auto step = [&](int t, int j, int jq) {
        const int j4 = (j + 4) & 7;

        // ---- critical scalar recurrence ----
        float x = fmaf(da, r, AxB[jq]);
        float alpha = __fdividef(1.f, 1.f + __expf(-x));
        float c = (1.f - alpha) * Vv[jq];
        float4 kk = KK[jq];
        r  = fmaf(alpha, A1, c * kk.x);
        A1 = fmaf(alpha, A2, c * kk.y);
        A2 = fmaf(alpha, A3, c * kk.z);

        // ---- throughput work: S update + two dots ----
        float h0=0.f, h1=0.f, d0=0.f, d1=0.f;
        #pragma unroll
        for (int jj = 0; jj < 8; jj++) {
            float s = fmaf(alpha, S[jj], c * K[j][jj]);
            S[jj] = s;
            if (jj & 1) { h1 = fmaf(s, Q[jq][jj], h1); d1 = fmaf(s, K[j4][jj], d1); }
            else        { h0 = fmaf(s, Q[jq][jj], h0); d0 = fmaf(s, K[j4][jj], d0); }
        }
        // interleaved reductions (independent chains pipeline)
        float h = h0 + h1, d = d0 + d1;
        h += __shfl_xor_sync(0xffffffffu, h, 1); d += __shfl_xor_sync(0xffffffffu, d, 1);
        h += __shfl_xor_sync(0xffffffffu, h, 2); d += __shfl_xor_sync(0xffffffffu, d, 2);
        h += __shfl_xor_sync(0xffffffffu, h, 4); d += __shfl_xor_sync(0xffffffffu, d, 4);
        A3 = d;   // S_t · k_{t+4}

        if (g == 0) {
            float sg = __fdividef(1.f, 1.f + __expf(-h));
            outp[0] = h * h * sg;            // h * silu(h)
        }
        outp += BATCH * NS;

        // ---- prefetch (after consumption of these slots) ----
        int tk = t + 8; if (tk > T_STEPS - 1) tk = T_STEPS - 1;
        int tq = t + 4; if (tq > T_STEPS - 1) tq = T_STEPS - 1;
        loadK(j, tk);
        loadQ(jq, tq);
        loadScal(jq, tq);
    };

    for (int t0 = 0; t0 < T_STEPS; t0 += 8) {
        step(t0 + 0, 0, 0);
        step(t0 + 1, 1, 1);
        step(t0 + 2, 2, 2);
        step(t0 + 3, 3, 3);
        step(t0 + 4, 4, 0);
        step(t0 + 5, 5, 1);
        step(t0 + 6, 6, 2);
        step(t0 + 7, 7, 3);
    }

    // S_final
    float* sf = out + (size_t)T_STEPS * BATCH * NS + ((size_t)b * NS + row) * NS + c0;
    #pragma unroll
    for (int j = 0; j < 8; j++) sf[j] = S[j];
}

// ---------------------------------------------------------------------------
extern "C" void kernel_launch(void* const* d_in, const int* in_sizes, int n_in,
                              void* d_out, int out_size) {
    const float* x  = (const float*)d_in[0];
    const float* S  = (const float*)d_in[1];
    const float* Wk = (const float*)d_in[2];
    const float* Wv = (const float*)d_in[3];
    const float* Wq = (const float*)d_in[4];
    const float* Wa = (const float*)d_in[5];
    const float* da = (const float*)d_in[6];
    const float* ba = (const float*)d_in[7];
    float* out = (float*)d_out;

    dim3 grid_gemm(M_TOT / 128, 4);
    proj_gemm<<<grid_gemm, 128>>>(x, Wk, Wq, Wv, Wa);
    kk_kernel<<<M_TOT / 128, 128>>>();
    scan_kernel<<<BATCH * 4, 128>>>(S, da, ba, out);
}

// round 6
// speedup vs baseline: 1.6207x; 1.6207x over previous
#include <cuda_runtime.h>
#include <cuda_bf16.h>
#include <cstdint>

#define T_STEPS 512
#define BATCH   32
#define DIM     1024
#define NS      64
#define M_TOT   (T_STEPS * BATCH)   // 16384

typedef unsigned long long ull;

// Scratch: projections [t][b][{k,q,v,ax}][64]  (16 MB, mostly L2-resident)
__device__ __align__(16) float  g_proj[(size_t)M_TOT * 256];
// kk[t][b] = { k_t·k_{t+1}, k_t·k_{t+2}, k_t·k_{t+3}, 0 }
__device__ __align__(16) float4 g_kk[M_TOT];

// ---------------------------------------------------------------------------
// Packed f32x2 FMA (Blackwell FFMA2: 2 fp32 FMA per instruction, same pipe)
// ---------------------------------------------------------------------------
__device__ __forceinline__ void ffma2(ull& d, ull a, ull b) {
    asm("fma.rn.f32x2 %0, %1, %2, %0;" : "+l"(d) : "l"(a), "l"(b));
}
__device__ __forceinline__ float2 upk(ull u) {
    float2 r; asm("mov.b64 {%0, %1}, %2;" : "=f"(r.x), "=f"(r.y) : "l"(u)); return r;
}

// ---------------------------------------------------------------------------
// Projection GEMM: C[m][n] = sum_d X[m][d] * W[n][d]
// grid (128, 4): y selects W (0=k,1=q,2=v,3=ax) -> column block y*64 of g_proj.
// BM=128, BN=64, BK=32, 128 threads, 8x8 per thread via FFMA2 on row-pairs.
// W tile stored duplicated {w,w} in a transposed slot order s = 8*(n&7)+(n>>3)
// so the inner-loop reads Wt[kk][8p+tx] are bank-conflict-free.
// ---------------------------------------------------------------------------
__global__ __launch_bounds__(128) void proj_gemm(
    const float* __restrict__ X,
    const float* __restrict__ Wk, const float* __restrict__ Wq,
    const float* __restrict__ Wv, const float* __restrict__ Wa)
{
    __shared__ float  Xs[32][128];   // [k][m]
    __shared__ float2 Wt[32][64];    // [k][slot], value duplicated in both halves

    const float* W = (blockIdx.y == 0) ? Wk :
                     (blockIdx.y == 1) ? Wq :
                     (blockIdx.y == 2) ? Wv : Wa;

    const int tid = threadIdx.x;
    const int m0  = blockIdx.x * 128;
    const int ty  = tid >> 3;   // 0..15 -> 8 m-rows (4 reg pairs)
    const int tx  = tid & 7;    // 0..7  -> 8 n-cols

    ull acc[4][8];               // [row-pair][col]; lo lane = even row
    #pragma unroll
    for (int i = 0; i < 4; i++)
        #pragma unroll
        for (int j = 0; j < 8; j++) acc[i][j] = 0ull;

    for (int k0 = 0; k0 < DIM; k0 += 32) {
        __syncthreads();
        // X tile 128x32: thread loads its row (m = m0+tid), 8 float4 across k
        #pragma unroll
        for (int i = 0; i < 8; i++) {
            float4 v = *(const float4*)(X + (size_t)(m0 + tid) * DIM + k0 + i * 4);
            Xs[i * 4 + 0][tid] = v.x;
            Xs[i * 4 + 1][tid] = v.y;
            Xs[i * 4 + 2][tid] = v.z;
            Xs[i * 4 + 3][tid] = v.w;
        }
        // W tile 64x32, duplicated + transposed-slot layout
        {
            int n    = tid & 63;
            int slot = ((n & 7) << 3) | (n >> 3);
            #pragma unroll
            for (int i = 0; i < 4; i++) {
                int kq = i * 2 + (tid >> 6);
                float4 v = *(const float4*)(W + (size_t)n * DIM + k0 + kq * 4);
                Wt[kq * 4 + 0][slot] = make_float2(v.x, v.x);
                Wt[kq * 4 + 1][slot] = make_float2(v.y, v.y);
                Wt[kq * 4 + 2][slot] = make_float2(v.z, v.z);
                Wt[kq * 4 + 3][slot] = make_float2(v.w, v.w);
            }
        }
        __syncthreads();

        #pragma unroll
        for (int kk = 0; kk < 32; kk++) {
            const ull* ar = (const ull*)&Xs[kk][ty * 8];
            ull ap0 = ar[0], ap1 = ar[1], ap2 = ar[2], ap3 = ar[3];
            ull wp[8];
            #pragma unroll
            for (int p = 0; p < 8; p++)
                wp[p] = *(const ull*)&Wt[kk][p * 8 + tx];   // col n = tx*8+p
            #pragma unroll
            for (int j = 0; j < 8; j++) {
                ffma2(acc[0][j], ap0, wp[j]);
                ffma2(acc[1][j], ap1, wp[j]);
                ffma2(acc[2][j], ap2, wp[j]);
                ffma2(acc[3][j], ap3, wp[j]);
            }
        }
    }

    // Store: row m = m0+ty*8+i, col = blockIdx.y*64 + tx*8 + j
    #pragma unroll
    for (int i = 0; i < 8; i++) {
        float c[8];
        #pragma unroll
        for (int j = 0; j < 8; j++) {
            float2 v = upk(acc[i >> 1][j]);
            c[j] = (i & 1) ? v.y : v.x;
        }
        float* dst = g_proj + (size_t)(m0 + ty * 8 + i) * 256 + blockIdx.y * 64 + tx * 8;
        *(float4*)(dst + 0) = make_float4(c[0], c[1], c[2], c[3]);
        *(float4*)(dst + 4) = make_float4(c[4], c[5], c[6], c[7]);
    }
}

// ---------------------------------------------------------------------------
// kk kernel: g_kk[t][b] = {k_t·k_{t+1}, k_t·k_{t+2}, k_t·k_{t+3}, 0}
// ---------------------------------------------------------------------------
__global__ __launch_bounds__(128) void kk_kernel()
{
    int idx = blockIdx.x * 128 + threadIdx.x;
    int t = idx >> 5, b = idx & 31;
    const float4* p0 = (const float4*)(g_proj + (size_t)(t * 32 + b) * 256);
    int t1 = (t + 1 < T_STEPS) ? t + 1 : t;
    int t2 = (t + 2 < T_STEPS) ? t + 2 : t;
    int t3 = (t + 3 < T_STEPS) ? t + 3 : t;
    const float4* p1 = (const float4*)(g_proj + (size_t)(t1 * 32 + b) * 256);
    const float4* p2 = (const float4*)(g_proj + (size_t)(t2 * 32 + b) * 256);
    const float4* p3 = (const float4*)(g_proj + (size_t)(t3 * 32 + b) * 256);
    float a1 = 0.f, a2 = 0.f, a3 = 0.f;
    #pragma unroll
    for (int i = 0; i < 16; i++) {
        float4 k0 = p0[i], q1 = p1[i], q2 = p2[i], q3 = p3[i];
        a1 += k0.x*q1.x + k0.y*q1.y + k0.z*q1.z + k0.w*q1.w;
        a2 += k0.x*q2.x + k0.y*q2.y + k0.z*q2.z + k0.w*q2.w;
        a3 += k0.x*q3.x + k0.y*q3.y + k0.z*q3.z + k0.w*q3.w;
    }
    if (t + 1 >= T_STEPS) a1 = 0.f;
    if (t + 2 >= T_STEPS) a2 = 0.f;
    if (t + 3 >= T_STEPS) a3 = 0.f;
    g_kk[idx] = make_float4(a1, a2, a3, 0.f);
}

// ---------------------------------------------------------------------------
// Scan with 3-level lookahead recurrence (validated in R3), now 256 thr/CTA
// so each SMSP runs 2 warps and stalls of one are filled by the other.
// Grid: 64 CTAs (2 per batch, 32 rows each), thread = (row, 8-col slice).
// ---------------------------------------------------------------------------
__global__ __launch_bounds__(256) void scan_kernel(
    const float* __restrict__ S_in,
    const float* __restrict__ d_alpha,
    const float* __restrict__ b_alpha,
    float* __restrict__ out)
{
    const int b   = blockIdx.x >> 1;
    const int rg  = blockIdx.x & 1;
    const int tid = threadIdx.x;
    const int rl  = tid >> 3;        // 0..31
    const int g   = tid & 7;
    const int row = rg * 32 + rl;
    const int c0  = g * 8;

    float S[8];
    {
        const float* sp = S_in + ((size_t)b * NS + row) * NS + c0;
        #pragma unroll
        for (int j = 0; j < 8; j++) S[j] = sp[j];
    }
    const float da = d_alpha[row];
    const float ba = b_alpha[row];

    float  K[8][8];
    float  Q[4][8];
    float4 KK[4];
    float  Vv[4], AxB[4];

    auto loadK = [&](int slot, int t) {
        const float4* p = (const float4*)(g_proj + (size_t)(t * 32 + b) * 256 + c0);
        float4 x0 = p[0], x1 = p[1];
        K[slot][0]=x0.x; K[slot][1]=x0.y; K[slot][2]=x0.z; K[slot][3]=x0.w;
        K[slot][4]=x1.x; K[slot][5]=x1.y; K[slot][6]=x1.z; K[slot][7]=x1.w;
    };
    auto loadQ = [&](int slot, int t) {
        const float4* p = (const float4*)(g_proj + (size_t)(t * 32 + b) * 256 + 64 + c0);
        float4 x0 = p[0], x1 = p[1];
        Q[slot][0]=x0.x; Q[slot][1]=x0.y; Q[slot][2]=x0.z; Q[slot][3]=x0.w;
        Q[slot][4]=x1.x; Q[slot][5]=x1.y; Q[slot][6]=x1.z; Q[slot][7]=x1.w;
    };
    auto loadScal = [&](int slot, int t) {
        size_t base = (size_t)(t * 32 + b) * 256;
        Vv[slot]  = g_proj[base + 128 + row];
        AxB[slot] = g_proj[base + 192 + row] + ba;
        KK[slot]  = g_kk[t * 32 + b];
    };
    auto red8 = [](float x) {
        x += __shfl_xor_sync(0xffffffffu, x, 1);
        x += __shfl_xor_sync(0xffffffffu, x, 2);
        x += __shfl_xor_sync(0xffffffffu, x, 4);
        return x;
    };

    #pragma unroll
    for (int j = 0; j < 8; j++) loadK(j, j);
    #pragma unroll
    for (int j = 0; j < 4; j++) { loadQ(j, j); loadScal(j, j); }

    float r, A1, A2, A3;
    {
        float t0=0.f, t1=0.f, t2=0.f, t3=0.f;
        #pragma unroll
        for (int j = 0; j < 8; j++) {
            t0 = fmaf(S[j], K[0][j], t0);
            t1 = fmaf(S[j], K[1][j], t1);
            t2 = fmaf(S[j], K[2][j], t2);
            t3 = fmaf(S[j], K[3][j], t3);
        }
        r = red8(t0); A1 = red8(t1); A2 = red8(t2); A3 = red8(t3);
    }

    float* outp = out + (size_t)b * NS + row;

    auto step = [&](int t, int j, int jq) {
        const int j4 = (j + 4) & 7;

        // ---- critical scalar recurrence ----
        float x = fmaf(da, r, AxB[jq]);
        float alpha = __fdividef(1.f, 1.f + __expf(-x));
        float c = (1.f - alpha) * Vv[jq];
        float4 kk = KK[jq];
        r  = fmaf(alpha, A1, c * kk.x);
        A1 = fmaf(alpha, A2, c * kk.y);
        A2 = fmaf(alpha, A3, c * kk.z);

        // ---- throughput work: S update + two dots ----
        float h0=0.f, h1=0.f, d0=0.f, d1=0.f;
        #pragma unroll
        for (int jj = 0; jj < 8; jj++) {
            float s = fmaf(alpha, S[jj], c * K[j][jj]);
            S[jj] = s;
            if (jj & 1) { h1 = fmaf(s, Q[jq][jj], h1); d1 = fmaf(s, K[j4][jj], d1); }
            else        { h0 = fmaf(s, Q[jq][jj], h0); d0 = fmaf(s, K[j4][jj], d0); }
        }
        float h = h0 + h1, d = d0 + d1;
        h += __shfl_xor_sync(0xffffffffu, h, 1); d += __shfl_xor_sync(0xffffffffu, d, 1);
        h += __shfl_xor_sync(0xffffffffu, h, 2); d += __shfl_xor_sync(0xffffffffu, d, 2);
        h += __shfl_xor_sync(0xffffffffu, h, 4); d += __shfl_xor_sync(0xffffffffu, d, 4);
        A3 = d;   // S_t · k_{t+4}, consumed 3 steps later

        if (g == 0) {
            float sg = __fdividef(1.f, 1.f + __expf(-h));
            outp[0] = h * h * sg;            // h * silu(h)
        }
        outp += BATCH * NS;

        int tk = t + 8; if (tk > T_STEPS - 1) tk = T_STEPS - 1;
        int tq = t + 4; if (tq > T_STEPS - 1) tq = T_STEPS - 1;
        loadK(j, tk);
        loadQ(jq, tq);
        loadScal(jq, tq);
    };

    for (int t0 = 0; t0 < T_STEPS; t0 += 8) {
        step(t0 + 0, 0, 0);
        step(t0 + 1, 1, 1);
        step(t0 + 2, 2, 2);
        step(t0 + 3, 3, 3);
        step(t0 + 4, 4, 0);
        step(t0 + 5, 5, 1);
        step(t0 + 6, 6, 2);
        step(t0 + 7, 7, 3);
    }

    float* sf = out + (size_t)T_STEPS * BATCH * NS + ((size_t)b * NS + row) * NS + c0;
    #pragma unroll
    for (int j = 0; j < 8; j++) sf[j] = S[j];
}

// ---------------------------------------------------------------------------
extern "C" void kernel_launch(void* const* d_in, const int* in_sizes, int n_in,
                              void* d_out, int out_size) {
    const float* x  = (const float*)d_in[0];
    const float* S  = (const float*)d_in[1];
    const float* Wk = (const float*)d_in[2];
    const float* Wv = (const float*)d_in[3];
    const float* Wq = (const float*)d_in[4];
    const float* Wa = (const float*)d_in[5];
    const float* da = (const float*)d_in[6];
    const float* ba = (const float*)d_in[7];
    float* out = (float*)d_out;

    dim3 grid_gemm(M_TOT / 128, 4);
    proj_gemm<<<grid_gemm, 128>>>(x, Wk, Wq, Wv, Wa);
    kk_kernel<<<M_TOT / 128, 128>>>();
    scan_kernel<<<BATCH * 2, 256>>>(S, da, ba, out);
}

// round 7
// speedup vs baseline: 3.4708x; 2.1415x over previous
#include <cuda_runtime.h>
#include <cuda_bf16.h>
#include <cstdint>

#define T_STEPS 512
#define BATCH   32
#define DIM     1024
#define NS      64
#define M_TOT   (T_STEPS * BATCH)   // 16384

// ---------------------------------------------------------------------------
// Device scratch
// ---------------------------------------------------------------------------
__device__ __align__(16) float  g_proj[(size_t)M_TOT * 256];   // [m][{k,q,v,ax}x64]
__device__ __align__(16) float4 g_kk[M_TOT];
__device__ __align__(16) __nv_bfloat16 g_Wh[256 * DIM];        // rows: k,q,v,ax
__device__ __align__(16) __nv_bfloat16 g_Wl[256 * DIM];

// ---------------------------------------------------------------------------
// helpers
// ---------------------------------------------------------------------------
__device__ __forceinline__ uint32_t smem_u32(const void* p) {
    uint32_t a;
    asm("{ .reg .u64 t; cvta.to.shared.u64 t, %1; cvt.u32.u64 %0, t; }" : "=r"(a) : "l"(p));
    return a;
}
// pack two fp32 -> bf16x2 (hi_elem -> high half), RN
__device__ __forceinline__ uint32_t bfpack(float hi_elem, float lo_elem) {
    uint32_t r;
    asm("cvt.rn.bf16x2.f32 %0, %1, %2;" : "=r"(r) : "f"(hi_elem), "f"(lo_elem));
    return r;
}
// swizzled byte offset inside a tile region (64B rows, 16B units)
__device__ __forceinline__ uint32_t swoff(int row, int unit) {
    return (uint32_t)(row * 64 + ((unit ^ ((row >> 1) & 3)) << 4));
}
__device__ __forceinline__ void cp16(uint32_t dst, const void* src) {
    asm volatile("cp.async.cg.shared.global [%0], [%1], 16;" :: "r"(dst), "l"(src) : "memory");
}
__device__ __forceinline__ void ldsm4(uint32_t* r, uint32_t a) {
    asm volatile("ldmatrix.sync.aligned.m8n8.x4.shared.b16 {%0,%1,%2,%3}, [%4];"
                 : "=r"(r[0]), "=r"(r[1]), "=r"(r[2]), "=r"(r[3]) : "r"(a));
}
__device__ __forceinline__ void ldsm2(uint32_t* r, uint32_t a) {
    asm volatile("ldmatrix.sync.aligned.m8n8.x2.shared.b16 {%0,%1}, [%2];"
                 : "=r"(r[0]), "=r"(r[1]) : "r"(a));
}
__device__ __forceinline__ void mma16816(float* c, const uint32_t* a, const uint32_t* b) {
    asm volatile(
        "mma.sync.aligned.m16n8k16.row.col.f32.bf16.bf16.f32 "
        "{%0,%1,%2,%3}, {%4,%5,%6,%7}, {%8,%9}, {%0,%1,%2,%3};"
        : "+f"(c[0]), "+f"(c[1]), "+f"(c[2]), "+f"(c[3])
        : "r"(a[0]), "r"(a[1]), "r"(a[2]), "r"(a[3]), "r"(b[0]), "r"(b[1]));
}

// ---------------------------------------------------------------------------
// Weight prep: split 4x[64,1024] fp32 into bf16 hi/lo, row order k,q,v,ax
// ---------------------------------------------------------------------------
__global__ __launch_bounds__(256) void prep_w(
    const float* __restrict__ Wk, const float* __restrict__ Wq,
    const float* __restrict__ Wv, const float* __restrict__ Wa)
{
    int idx = blockIdx.x * 256 + threadIdx.x;     // 0..65535 (float4 granules)
    int r = idx >> 8, c4 = idx & 255;
    const float* W = (r < 64) ? Wk : (r < 128) ? Wq : (r < 192) ? Wv : Wa;
    float4 v = ((const float4*)(W + (size_t)(r & 63) * DIM))[c4];
    uint32_t h01 = bfpack(v.y, v.x);
    uint32_t h23 = bfpack(v.w, v.z);
    float l0 = v.x - __uint_as_float(h01 << 16);
    float l1 = v.y - __uint_as_float(h01 & 0xffff0000u);
    float l2 = v.z - __uint_as_float(h23 << 16);
    float l3 = v.w - __uint_as_float(h23 & 0xffff0000u);
    ((uint2*)g_Wh)[idx] = make_uint2(h01, h23);
    ((uint2*)g_Wl)[idx] = make_uint2(bfpack(l1, l0), bfpack(l3, l2));
}

// ---------------------------------------------------------------------------
// Tensor-core projection GEMM (mma.sync bf16x3):
// C[16384,256] = X[16384,1024] (fp32, split on the fly) x W^T (pre-split).
// Grid 128 CTAs x 512 thr; CTA tile 128x256; warp (wm=wid&3, wn=wid>>2)
// tile 32x64.  K chunks of 32, double-buffered smem, cp.async for W.
// Stage layout (48KB): Ah @0 (8K), Al @8K, Bh @16K (16K), Bl @32K.
// ---------------------------------------------------------------------------
#define STAGE_BYTES 49152
#define GEMM_SMEM   (2 * STAGE_BYTES)

__global__ __launch_bounds__(512) void proj_gemm_mma(const float* __restrict__ X)
{
    extern __shared__ char sm[];
    const uint32_t sb = smem_u32(sm);
    const int tid  = threadIdx.x;
    const int lane = tid & 31;
    const int wid  = tid >> 5;
    const int wm   = wid & 3;          // m block (32 rows)
    const int wn   = wid >> 2;         // n block (64 cols) == weight index
    const int m0   = blockIdx.x * 128;

    float c[2][8][4];
    #pragma unroll
    for (int i = 0; i < 2; i++)
        #pragma unroll
        for (int j = 0; j < 8; j++)
            #pragma unroll
            for (int q = 0; q < 4; q++) c[i][j][q] = 0.f;

    const int xrow = tid >> 2, xu = tid & 3;           // X staging role
    const int wp   = tid >> 8, wrow = tid & 255;       // W staging role

    auto issueW = [&](int ch, int s) {
        const __nv_bfloat16* src = (wp ? g_Wl : g_Wh) + (size_t)wrow * DIM + ch * 32;
        uint32_t dbase = sb + s * STAGE_BYTES + 16384 + wp * 16384;
        #pragma unroll
        for (int u = 0; u < 4; u++) cp16(dbase + swoff(wrow, u), src + u * 8);
        asm volatile("cp.async.commit_group;" ::: "memory");
    };
    float4 xa, xb;
    auto loadX = [&](int ch) {
        const float* p = X + (size_t)(m0 + xrow) * DIM + ch * 32 + xu * 8;
        xa = *(const float4*)p;
        xb = *(const float4*)(p + 4);
    };
    auto stsX = [&](int s) {
        uint32_t h01 = bfpack(xa.y, xa.x), h23 = bfpack(xa.w, xa.z);
        uint32_t h45 = bfpack(xb.y, xb.x), h67 = bfpack(xb.w, xb.z);
        float l0 = xa.x - __uint_as_float(h01 << 16);
        float l1 = xa.y - __uint_as_float(h01 & 0xffff0000u);
        float l2 = xa.z - __uint_as_float(h23 << 16);
        float l3 = xa.w - __uint_as_float(h23 & 0xffff0000u);
        float l4 = xb.x - __uint_as_float(h45 << 16);
        float l5 = xb.y - __uint_as_float(h45 & 0xffff0000u);
        float l6 = xb.z - __uint_as_float(h67 << 16);
        float l7 = xb.w - __uint_as_float(h67 & 0xffff0000u);
        uint32_t off = s * STAGE_BYTES + swoff(xrow, xu);
        *(uint4*)(sm + off)        = make_uint4(h01, h23, h45, h67);
        *(uint4*)(sm + off + 8192) = make_uint4(bfpack(l1, l0), bfpack(l3, l2),
                                                bfpack(l5, l4), bfpack(l7, l6));
    };

    // prologue
    issueW(0, 0);
    loadX(0);

    for (int ch = 0; ch < 32; ch++) {
        const int s = ch & 1;
        asm volatile("cp.async.wait_group 0;" ::: "memory");
        stsX(s);
        if (ch + 1 < 32) { issueW(ch + 1, s ^ 1); loadX(ch + 1); }
        __syncthreads();

        const uint32_t st = sb + s * STAGE_BYTES;
        #pragma unroll
        for (int kt = 0; kt < 2; kt++) {
            uint32_t ah[2][4], al[2][4];
            #pragma unroll
            for (int mt = 0; mt < 2; mt++) {
                uint32_t aoff = swoff(wm * 32 + mt * 16 + (lane & 15), kt * 2 + (lane >> 4));
                ldsm4(ah[mt], st + aoff);
                ldsm4(al[mt], st + 8192 + aoff);
            }
            #pragma unroll
            for (int nt = 0; nt < 8; nt++) {
                uint32_t boff = swoff(wn * 64 + nt * 8 + (lane & 7),
                                      kt * 2 + ((lane >> 3) & 1));
                uint32_t bh[2], bl[2];
                ldsm2(bh, st + 16384 + boff);
                ldsm2(bl, st + 32768 + boff);
                mma16816(c[0][nt], ah[0], bh);
                mma16816(c[1][nt], ah[1], bh);
                mma16816(c[0][nt], al[0], bh);
                mma16816(c[1][nt], al[1], bh);
                mma16816(c[0][nt], ah[0], bl);
                mma16816(c[1][nt], ah[1], bl);
            }
        }
        __syncthreads();
    }

    // epilogue: fragment -> g_proj
    #pragma unroll
    for (int mt = 0; mt < 2; mt++) {
        #pragma unroll
        for (int nt = 0; nt < 8; nt++) {
            int m = m0 + wm * 32 + mt * 16 + (lane >> 2);
            int n = wn * 64 + nt * 8 + (lane & 3) * 2;
            *(float2*)&g_proj[(size_t)m * 256 + n]       = make_float2(c[mt][nt][0], c[mt][nt][1]);
            *(float2*)&g_proj[(size_t)(m + 8) * 256 + n] = make_float2(c[mt][nt][2], c[mt][nt][3]);
        }
    }
}

// ---------------------------------------------------------------------------
// kk kernel: g_kk[t][b] = {k_t·k_{t+1}, k_t·k_{t+2}, k_t·k_{t+3}, 0}
// ---------------------------------------------------------------------------
__global__ __launch_bounds__(128) void kk_kernel()
{
    int idx = blockIdx.x * 128 + threadIdx.x;
    int t = idx >> 5, b = idx & 31;
    const float4* p0 = (const float4*)(g_proj + (size_t)(t * 32 + b) * 256);
    int t1 = (t + 1 < T_STEPS) ? t + 1 : t;
    int t2 = (t + 2 < T_STEPS) ? t + 2 : t;
    int t3 = (t + 3 < T_STEPS) ? t + 3 : t;
    const float4* p1 = (const float4*)(g_proj + (size_t)(t1 * 32 + b) * 256);
    const float4* p2 = (const float4*)(g_proj + (size_t)(t2 * 32 + b) * 256);
    const float4* p3 = (const float4*)(g_proj + (size_t)(t3 * 32 + b) * 256);
    float a1 = 0.f, a2 = 0.f, a3 = 0.f;
    #pragma unroll
    for (int i = 0; i < 16; i++) {
        float4 k0 = p0[i], q1 = p1[i], q2 = p2[i], q3 = p3[i];
        a1 += k0.x*q1.x + k0.y*q1.y + k0.z*q1.z + k0.w*q1.w;
        a2 += k0.x*q2.x + k0.y*q2.y + k0.z*q2.z + k0.w*q2.w;
        a3 += k0.x*q3.x + k0.y*q3.y + k0.z*q3.z + k0.w*q3.w;
    }
    if (t + 1 >= T_STEPS) a1 = 0.f;
    if (t + 2 >= T_STEPS) a2 = 0.f;
    if (t + 3 >= T_STEPS) a3 = 0.f;
    g_kk[idx] = make_float4(a1, a2, a3, 0.f);
}

// ---------------------------------------------------------------------------
// Scan with 3-level lookahead recurrence (R3-validated config:
// 128 CTAs x 128 threads, thread = (row, 8-col slice))
// ---------------------------------------------------------------------------
__global__ __launch_bounds__(128) void scan_kernel(
    const float* __restrict__ S_in,
    const float* __restrict__ d_alpha,
    const float* __restrict__ b_alpha,
    float* __restrict__ out)
{
    const int b   = blockIdx.x >> 2;
    const int rg  = blockIdx.x & 3;
    const int tid = threadIdx.x;
    const int rl  = tid >> 3;
    const int g   = tid & 7;
    const int row = rg * 16 + rl;
    const int c0  = g * 8;

    float S[8];
    {
        const float* sp = S_in + ((size_t)b * NS + row) * NS + c0;
        #pragma unroll
        for (int j = 0; j < 8; j++) S[j] = sp[j];
    }
    const float da = d_alpha[row];
    const float ba = b_alpha[row];

    float  K[8][8];
    float  Q[4][8];
    float4 KK[4];
    float  Vv[4], AxB[4];

    auto loadK = [&](int slot, int t) {
        const float4* p = (const float4*)(g_proj + (size_t)(t * 32 + b) * 256 + c0);
        float4 x0 = p[0], x1 = p[1];
        K[slot][0]=x0.x; K[slot][1]=x0.y; K[slot][2]=x0.z; K[slot][3]=x0.w;
        K[slot][4]=x1.x; K[slot][5]=x1.y; K[slot][6]=x1.z; K[slot][7]=x1.w;
    };
    auto loadQ = [&](int slot, int t) {
        const float4* p = (const float4*)(g_proj + (size_t)(t * 32 + b) * 256 + 64 + c0);
        float4 x0 = p[0], x1 = p[1];
        Q[slot][0]=x0.x; Q[slot][1]=x0.y; Q[slot][2]=x0.z; Q[slot][3]=x0.w;
        Q[slot][4]=x1.x; Q[slot][5]=x1.y; Q[slot][6]=x1.z; Q[slot][7]=x1.w;
    };
    auto loadScal = [&](int slot, int t) {
        size_t base = (size_t)(t * 32 + b) * 256;
        Vv[slot]  = g_proj[base + 128 + row];
        AxB[slot] = g_proj[base + 192 + row] + ba;
        KK[slot]  = g_kk[t * 32 + b];
    };
    auto red8 = [](float x) {
        x += __shfl_xor_sync(0xffffffffu, x, 1);
        x += __shfl_xor_sync(0xffffffffu, x, 2);
        x += __shfl_xor_sync(0xffffffffu, x, 4);
        return x;
    };

    #pragma unroll
    for (int j = 0; j < 8; j++) loadK(j, j);
    #pragma unroll
    for (int j = 0; j < 4; j++) { loadQ(j, j); loadScal(j, j); }

    float r, A1, A2, A3;
    {
        float t0=0.f, t1=0.f, t2=0.f, t3=0.f;
        #pragma unroll
        for (int j = 0; j < 8; j++) {
            t0 = fmaf(S[j], K[0][j], t0);
            t1 = fmaf(S[j], K[1][j], t1);
            t2 = fmaf(S[j], K[2][j], t2);
            t3 = fmaf(S[j], K[3][j], t3);
        }
        r = red8(t0); A1 = red8(t1); A2 = red8(t2); A3 = red8(t3);
    }

    float* outp = out + (size_t)b * NS + row;

    auto step = [&](int t, int j, int jq) {
        const int j4 = (j + 4) & 7;

        float x = fmaf(da, r, AxB[jq]);
        float alpha = __fdividef(1.f, 1.f + __expf(-x));
        float c = (1.f - alpha) * Vv[jq];
        float4 kk = KK[jq];
        r  = fmaf(alpha, A1, c * kk.x);
        A1 = fmaf(alpha, A2, c * kk.y);
        A2 = fmaf(alpha, A3, c * kk.z);

        float h0=0.f, h1=0.f, d0=0.f, d1=0.f;
        #pragma unroll
        for (int jj = 0; jj < 8; jj++) {
            float s = fmaf(alpha, S[jj], c * K[j][jj]);
            S[jj] = s;
            if (jj & 1) { h1 = fmaf(s, Q[jq][jj], h1); d1 = fmaf(s, K[j4][jj], d1); }
            else        { h0 = fmaf(s, Q[jq][jj], h0); d0 = fmaf(s, K[j4][jj], d0); }
        }
        float h = h0 + h1, d = d0 + d1;
        h += __shfl_xor_sync(0xffffffffu, h, 1); d += __shfl_xor_sync(0xffffffffu, d, 1);
        h += __shfl_xor_sync(0xffffffffu, h, 2); d += __shfl_xor_sync(0xffffffffu, d, 2);
        h += __shfl_xor_sync(0xffffffffu, h, 4); d += __shfl_xor_sync(0xffffffffu, d, 4);
        A3 = d;

        if (g == 0) {
            float sg = __fdividef(1.f, 1.f + __expf(-h));
            outp[0] = h * h * sg;
        }
        outp += BATCH * NS;

        int tk = t + 8; if (tk > T_STEPS - 1) tk = T_STEPS - 1;
        int tq = t + 4; if (tq > T_STEPS - 1) tq = T_STEPS - 1;
        loadK(j, tk);
        loadQ(jq, tq);
        loadScal(jq, tq);
    };

    for (int t0 = 0; t0 < T_STEPS; t0 += 8) {
        step(t0 + 0, 0, 0);
        step(t0 + 1, 1, 1);
        step(t0 + 2, 2, 2);
        step(t0 + 3, 3, 3);
        step(t0 + 4, 4, 0);
        step(t0 + 5, 5, 1);
        step(t0 + 6, 6, 2);
        step(t0 + 7, 7, 3);
    }

    float* sf = out + (size_t)T_STEPS * BATCH * NS + ((size_t)b * NS + row) * NS + c0;
    #pragma unroll
    for (int j = 0; j < 8; j++) sf[j] = S[j];
}

// ---------------------------------------------------------------------------
extern "C" void kernel_launch(void* const* d_in, const int* in_sizes, int n_in,
                              void* d_out, int out_size) {
    const float* x  = (const float*)d_in[0];
    const float* S  = (const float*)d_in[1];
    const float* Wk = (const float*)d_in[2];
    const float* Wv = (const float*)d_in[3];
    const float* Wq = (const float*)d_in[4];
    const float* Wa = (const float*)d_in[5];
    const float* da = (const float*)d_in[6];
    const float* ba = (const float*)d_in[7];
    float* out = (float*)d_out;

    cudaFuncSetAttribute(proj_gemm_mma, cudaFuncAttributeMaxDynamicSharedMemorySize, GEMM_SMEM);

    prep_w<<<256, 256>>>(Wk, Wq, Wv, Wa);
    proj_gemm_mma<<<M_TOT / 128, 512, GEMM_SMEM>>>(x);
    kk_kernel<<<M_TOT / 128, 128>>>();
    scan_kernel<<<BATCH * 4, 128>>>(S, da, ba, out);
}